// round 1
// baseline (speedup 1.0000x reference)
#include <cuda_runtime.h>

// Problem dims
#define N_  20000
#define K_  20
#define T_  50
#define D_  200
#define T2  25          // t-pairs (f32x2 packing over the fastest axis)
#define NT  32          // n rows per block
#define DC  10          // d chunk size (200/10 = 20 chunks)
#define NNN 4           // n rows per thread
#define GRP (NT/NNN)    // 8 groups
#define CTH (GRP*T2)    // 200 compute threads
#define BLK 256
#define EPSF 1e-8f

typedef unsigned long long u64;

// Precomputed sigmoid(phi), filled by kernel 1, read by kernel 2.
__device__ float g_phiprob[K_ * D_ * T_];

__device__ __forceinline__ u64 ffma2(u64 a, u64 b, u64 c) {
    u64 d;
    asm("fma.rn.f32x2 %0, %1, %2, %3;" : "=l"(d) : "l"(a), "l"(b), "l"(c));
    return d;
}

__global__ void phi_sigmoid_kernel(const float* __restrict__ phi,
                                   float* __restrict__ out_phi) {
    int i = blockIdx.x * blockDim.x + threadIdx.x;
    if (i < K_ * D_ * T_) {
        float p = __fdividef(1.f, 1.f + __expf(-phi[i]));
        out_phi[i]   = p;
        g_phiprob[i] = p;
    }
}

__global__ __launch_bounds__(BLK) void main_kernel(
    const float* __restrict__ lambda_,
    float* __restrict__ pi_out,
    float* __restrict__ theta_out)
{
    extern __shared__ float2 smem[];
    float2* theta_s = smem;                // [K_][NT][T2]  = 128000 B
    float2* phi_s   = smem + K_ * NT * T2; // [K_][DC][T2]  =  40000 B

    const int nbase = blockIdx.x * NT;
    const float2* lam2 = (const float2*)lambda_;
    float2*       th2  = (float2*)theta_out;
    float2*       pi2  = (float2*)pi_out;
    const float2* pp2  = (const float2*)g_phiprob;

    // ---------------- Stage 1: softmax over K for this block's 32 n's ----------------
    for (int cell = threadIdx.x; cell < NT * T2; cell += BLK) {
        int t2 = cell % T2;
        int n  = cell / T2;
        size_t base = (size_t)(nbase + n) * K_ * T2 + t2;   // float2 index of (n, k=0, t=2*t2)

        float2 v[K_];
        #pragma unroll
        for (int k = 0; k < K_; k++) v[k] = lam2[base + (size_t)k * T2];

        float mx = v[0].x, my = v[0].y;
        #pragma unroll
        for (int k = 1; k < K_; k++) { mx = fmaxf(mx, v[k].x); my = fmaxf(my, v[k].y); }

        float sx = 0.f, sy = 0.f;
        #pragma unroll
        for (int k = 0; k < K_; k++) {
            v[k].x = __expf(v[k].x - mx);
            v[k].y = __expf(v[k].y - my);
            sx += v[k].x; sy += v[k].y;
        }
        float ix = __fdividef(1.f, sx), iy = __fdividef(1.f, sy);

        #pragma unroll
        for (int k = 0; k < K_; k++) {
            float2 th; th.x = v[k].x * ix; th.y = v[k].y * iy;
            theta_s[(k * NT + n) * T2 + t2] = th;       // [k][n][t2], t2-fastest
            th2[base + (size_t)k * T2] = th;            // coalesced global write
        }
    }
    __syncthreads();

    const int t2c = threadIdx.x % T2;
    const int g   = threadIdx.x / T2;
    const int n0  = g * NNN;

    // ---------------- Stage 2: d-chunked contraction ----------------
    for (int dch = 0; dch < D_ / DC; dch++) {
        const int d0 = dch * DC;

        // Stage phi_prob chunk [K_][DC][T2] into shared (all 256 threads)
        for (int i = threadIdx.x; i < K_ * DC * T2; i += BLK) {
            int t2 = i % T2;
            int r  = i / T2;
            int d  = r % DC;
            int k  = r / DC;
            phi_s[(k * DC + d) * T2 + t2] =
                pp2[((size_t)k * D_ + d0 + d) * T2 + t2];
        }
        __syncthreads();

        if (threadIdx.x < CTH) {
            u64 acc[NNN][DC];
            #pragma unroll
            for (int i = 0; i < NNN; i++)
                #pragma unroll
                for (int d = 0; d < DC; d++) acc[i][d] = 0ull;

            #pragma unroll
            for (int k = 0; k < K_; k++) {
                u64 th[NNN], ph[DC];
                #pragma unroll
                for (int i = 0; i < NNN; i++)
                    th[i] = *(const u64*)&theta_s[(k * NT + n0 + i) * T2 + t2c];
                #pragma unroll
                for (int d = 0; d < DC; d++)
                    ph[d] = *(const u64*)&phi_s[(k * DC + d) * T2 + t2c];
                #pragma unroll
                for (int i = 0; i < NNN; i++)
                    #pragma unroll
                    for (int d = 0; d < DC; d++)
                        acc[i][d] = ffma2(th[i], ph[d], acc[i][d]);
            }

            #pragma unroll
            for (int i = 0; i < NNN; i++) {
                #pragma unroll
                for (int d = 0; d < DC; d++) {
                    float2 f;
                    asm("mov.b64 {%0, %1}, %2;" : "=f"(f.x), "=f"(f.y) : "l"(acc[i][d]));
                    f.x = fminf(fmaxf(f.x, EPSF), 1.f - EPSF);
                    f.y = fminf(fmaxf(f.y, EPSF), 1.f - EPSF);
                    pi2[((size_t)(nbase + n0 + i) * D_ + d0 + d) * T2 + t2c] = f;
                }
            }
        }
        __syncthreads();   // protect phi_s before next chunk's staging
    }
}

extern "C" void kernel_launch(void* const* d_in, const int* in_sizes, int n_in,
                              void* d_out, int out_size) {
    const float* lambda_ = (const float*)d_in[0];   // [N, K, T] = 20,000,000 floats
    const float* phi     = (const float*)d_in[1];   // [K, D, T] =    200,000 floats

    float* out         = (float*)d_out;
    float* pi_out      = out;                                        // 200,000,000
    float* theta_out   = out + (size_t)N_ * D_ * T_;                 //  20,000,000
    float* phiprob_out = theta_out + (size_t)N_ * K_ * T_;           //     200,000

    // Kernel 1: sigmoid(phi) -> output region + device scratch
    phi_sigmoid_kernel<<<(K_ * D_ * T_ + 255) / 256, 256>>>(phi, phiprob_out);

    // Kernel 2: fused softmax + contraction
    size_t smem_bytes = sizeof(float2) * (size_t)(K_ * NT * T2 + K_ * DC * T2); // 168000 B
    cudaFuncSetAttribute(main_kernel, cudaFuncAttributeMaxDynamicSharedMemorySize,
                         (int)smem_bytes);
    main_kernel<<<N_ / NT, BLK, smem_bytes>>>(lambda_, pi_out, theta_out);
}

// round 2
// speedup vs baseline: 1.1983x; 1.1983x over previous
#include <cuda_runtime.h>

// Problem dims
#define N_  20000
#define K_  20
#define T_  50
#define D_  200
#define T2  25          // t-pairs (f32x2 packing over the fastest axis)
#define NT  32          // n rows per block
#define DC  8           // d chunk size (25 chunks of 8)
#define NNN 4           // n rows per compute thread
#define GRP (NT/NNN)    // 8 groups of t2-lanes
#define CTH (GRP*T2)    // 200 compute threads per half-block
#define HBLK 256        // threads per d-group
#define BLK  512        // two d-groups per block
#define NCHUNK (D_/DC)  // 25
#define EPSF 1e-8f

typedef unsigned long long u64;

// Precomputed sigmoid(phi), filled by kernel 1, read by kernel 2.
__device__ float g_phiprob[K_ * D_ * T_];

__device__ __forceinline__ u64 ffma2(u64 a, u64 b, u64 c) {
    u64 d;
    asm("fma.rn.f32x2 %0, %1, %2, %3;" : "=l"(d) : "l"(a), "l"(b), "l"(c));
    return d;
}

__device__ __forceinline__ void group_bar(int bar_id) {
    asm volatile("bar.sync %0, %1;" :: "r"(bar_id), "r"(HBLK) : "memory");
}

__global__ void phi_sigmoid_kernel(const float* __restrict__ phi,
                                   float* __restrict__ out_phi) {
    int i = blockIdx.x * blockDim.x + threadIdx.x;
    if (i < K_ * D_ * T_) {
        float p = __fdividef(1.f, 1.f + __expf(-phi[i]));
        out_phi[i]   = p;
        g_phiprob[i] = p;
    }
}

__global__ __launch_bounds__(BLK) void main_kernel(
    const float* __restrict__ lambda_,
    float* __restrict__ pi_out,
    float* __restrict__ theta_out)
{
    extern __shared__ float2 smem[];
    float2* theta_s = smem;                       // [K_][NT][T2]      = 128000 B
    float2* phi_sA  = smem + K_ * NT * T2;        // [K_][DC][T2] grp0 =  32000 B
    float2* phi_sB  = phi_sA + K_ * DC * T2;      // [K_][DC][T2] grp1 =  32000 B

    const int tid   = threadIdx.x;
    const int nbase = blockIdx.x * NT;
    const float2* lam2 = (const float2*)lambda_;
    float2*       th2  = (float2*)theta_out;
    float2*       pi2  = (float2*)pi_out;
    const float2* pp2  = (const float2*)g_phiprob;

    // ---------------- Stage 1: softmax over K for this block's 32 n's (all 512 threads) ----
    for (int cell = tid; cell < NT * T2; cell += BLK) {
        int t2 = cell % T2;
        int n  = cell / T2;
        size_t base = (size_t)(nbase + n) * K_ * T2 + t2;   // float2 index of (n, k=0, t=2*t2)

        float2 v[K_];
        #pragma unroll
        for (int k = 0; k < K_; k++) v[k] = lam2[base + (size_t)k * T2];

        float mx = v[0].x, my = v[0].y;
        #pragma unroll
        for (int k = 1; k < K_; k++) { mx = fmaxf(mx, v[k].x); my = fmaxf(my, v[k].y); }

        float sx = 0.f, sy = 0.f;
        #pragma unroll
        for (int k = 0; k < K_; k++) {
            v[k].x = __expf(v[k].x - mx);
            v[k].y = __expf(v[k].y - my);
            sx += v[k].x; sy += v[k].y;
        }
        float ix = __fdividef(1.f, sx), iy = __fdividef(1.f, sy);

        #pragma unroll
        for (int k = 0; k < K_; k++) {
            float2 th; th.x = v[k].x * ix; th.y = v[k].y * iy;
            theta_s[(k * NT + n) * T2 + t2] = th;       // [k][n][t2], t2-fastest
            th2[base + (size_t)k * T2] = th;            // coalesced global write
        }
    }
    __syncthreads();

    // ---------------- Stage 2: d-chunked contraction, two independent 256-thread groups ----
    const int gsel = tid / HBLK;            // 0 or 1 (warp-aligned split)
    const int ltid = tid % HBLK;
    float2* phi_s  = gsel ? phi_sB : phi_sA;
    const int bar  = 1 + gsel;

    // group 0: chunks [0,13)   group 1: chunks [13,25)
    const int c_lo = gsel ? 13 : 0;
    const int c_hi = gsel ? NCHUNK : 13;

    const int t2c = ltid % T2;
    const int g   = ltid / T2;              // 0..7 (and 8..10 inactive lanes)
    const int n0  = g * NNN;

    for (int chunk = c_lo; chunk < c_hi; chunk++) {
        const int d0 = chunk * DC;

        // Stage this group's phi_prob chunk [K_][DC][T2] (256 threads)
        for (int i = ltid; i < K_ * DC * T2; i += HBLK) {
            int t2 = i % T2;
            int r  = i / T2;
            int d  = r % DC;
            int k  = r / DC;
            phi_s[(k * DC + d) * T2 + t2] =
                pp2[((size_t)k * D_ + d0 + d) * T2 + t2];
        }
        group_bar(bar);

        if (ltid < CTH) {
            u64 acc[NNN][DC];
            #pragma unroll
            for (int i = 0; i < NNN; i++)
                #pragma unroll
                for (int d = 0; d < DC; d++) acc[i][d] = 0ull;

            #pragma unroll
            for (int k = 0; k < K_; k++) {
                u64 th[NNN], ph[DC];
                #pragma unroll
                for (int i = 0; i < NNN; i++)
                    th[i] = *(const u64*)&theta_s[(k * NT + n0 + i) * T2 + t2c];
                #pragma unroll
                for (int d = 0; d < DC; d++)
                    ph[d] = *(const u64*)&phi_s[(k * DC + d) * T2 + t2c];
                #pragma unroll
                for (int i = 0; i < NNN; i++)
                    #pragma unroll
                    for (int d = 0; d < DC; d++)
                        acc[i][d] = ffma2(th[i], ph[d], acc[i][d]);
            }

            #pragma unroll
            for (int i = 0; i < NNN; i++) {
                #pragma unroll
                for (int d = 0; d < DC; d++) {
                    float2 f;
                    asm("mov.b64 {%0, %1}, %2;" : "=f"(f.x), "=f"(f.y) : "l"(acc[i][d]));
                    f.x = fminf(fmaxf(f.x, EPSF), 1.f - EPSF);
                    f.y = fminf(fmaxf(f.y, EPSF), 1.f - EPSF);
                    pi2[((size_t)(nbase + n0 + i) * D_ + d0 + d) * T2 + t2c] = f;
                }
            }
        }
        group_bar(bar);   // protect phi_s before next chunk's staging
    }
}

extern "C" void kernel_launch(void* const* d_in, const int* in_sizes, int n_in,
                              void* d_out, int out_size) {
    const float* lambda_ = (const float*)d_in[0];   // [N, K, T] = 20,000,000 floats
    const float* phi     = (const float*)d_in[1];   // [K, D, T] =    200,000 floats

    float* out         = (float*)d_out;
    float* pi_out      = out;                                        // 200,000,000
    float* theta_out   = out + (size_t)N_ * D_ * T_;                 //  20,000,000
    float* phiprob_out = theta_out + (size_t)N_ * K_ * T_;           //     200,000

    // Kernel 1: sigmoid(phi) -> output region + device scratch
    phi_sigmoid_kernel<<<(K_ * D_ * T_ + 255) / 256, 256>>>(phi, phiprob_out);

    // Kernel 2: fused softmax + contraction
    size_t smem_bytes = sizeof(float2) * (size_t)(K_ * NT * T2 + 2 * K_ * DC * T2); // 192000 B
    cudaFuncSetAttribute(main_kernel, cudaFuncAttributeMaxDynamicSharedMemorySize,
                         (int)smem_bytes);
    main_kernel<<<N_ / NT, BLK, smem_bytes>>>(lambda_, pi_out, theta_out);
}